// round 8
// baseline (speedup 1.0000x reference)
#include <cuda_runtime.h>
#include <math.h>
typedef unsigned long long ull;
typedef ulonglong2 ull2;

#define NTH 512
#define TST 1024
#define BATCH 1024
#define EPSF 1e-8f

// ---- SMEM layout (float offsets) ----
#define W10O 0          // 128*71, w[j*71+k]
#define W20O 9088
#define W11S 18176      // 128*132, w[j*132+(k&3)*33+(k>>2)]
#define W21S 35072
#define BIAS 51968      // b10,b20,b11,b21,b12,b22 (6*128)
#define WOUTO 52736     // 384
#define ACTo 53120      // [q2][70][4], quad stride 280: [xn(6)|h(64)]
#define SCRA 53680      // [q2][128][4], quad stride 516
#define SCRB 54712
#define XBo 55744       // 48
#define NBo 55792       // 8
#define SMF 55800       // 223,200 B

__device__ __forceinline__ ull pack2(float lo, float hi){ull r;asm("mov.b64 %0,{%1,%2};":"=l"(r):"f"(lo),"f"(hi));return r;}
__device__ __forceinline__ void unpack2(ull v,float&lo,float&hi){asm("mov.b64 {%0,%1},%2;":"=f"(lo),"=f"(hi):"l"(v));}
__device__ __forceinline__ void ffma2(ull&d,ull a,ull b){asm("fma.rn.f32x2 %0,%1,%2,%0;":"+l"(d):"l"(a),"l"(b));}
__device__ __forceinline__ ull addx2(ull a,ull b){ull r;asm("add.rn.f32x2 %0,%1,%2;":"=l"(r):"l"(a),"l"(b));return r;}
__device__ __forceinline__ ull mulx2(ull a,ull b){ull r;asm("mul.rn.f32x2 %0,%1,%2;":"=l"(r):"l"(a),"l"(b));return r;}
__device__ __forceinline__ ull shflx(ull v, int m){
    unsigned lo = (unsigned)v, hi = (unsigned)(v >> 32);
    lo = __shfl_xor_sync(0xffffffffu, lo, m);
    hi = __shfl_xor_sync(0xffffffffu, hi, m);
    return ((ull)hi << 32) | lo;
}
__device__ __forceinline__ void red1(ull&a){ a = addx2(a, shflx(a,1)); }
__device__ __forceinline__ ull sel4(ull a0, ull a1, ull a2, ull a3, int c){
    ull x = (c&1) ? a1 : a0; ull y = (c&1) ? a3 : a2; return (c&2) ? y : x;
}

__global__ void __launch_bounds__(NTH, 1)
lmsc_kernel(const float* __restrict__ x, const float* __restrict__ initF,
            const float* __restrict__ w10,const float* __restrict__ b10,
            const float* __restrict__ w20,const float* __restrict__ b20,
            const float* __restrict__ w11,const float* __restrict__ b11,
            const float* __restrict__ w21,const float* __restrict__ b21,
            const float* __restrict__ w12,const float* __restrict__ b12,
            const float* __restrict__ w22,const float* __restrict__ b22,
            const float* __restrict__ wa, const float* __restrict__ ba,
            const float* __restrict__ wb, const float* __restrict__ bb,
            const float* __restrict__ wout,float* __restrict__ out)
{
    extern __shared__ float sm[];
    const int tid = threadIdx.x;
    const int b0 = blockIdx.x * 8;
    const int j = tid >> 2, c = tid & 3;      // matvec phases
    const int jq = tid >> 3, c8 = tid & 7;    // heads phase

    // ---- init ----
    for (int idx = tid; idx < 70*128; idx += NTH) {
        int k = idx >> 7, jj = idx & 127;
        sm[W10O + jj*71 + k] = w10[idx];
        sm[W20O + jj*71 + k] = w20[idx];
    }
    for (int idx = tid; idx < 128*128; idx += NTH) {
        int k = idx >> 7, jj = idx & 127;
        int pos = jj*132 + (k&3)*33 + (k>>2);
        sm[W11S + pos] = w11[idx];
        sm[W21S + pos] = w21[idx];
    }
    if (tid < 128) {
        sm[BIAS      + tid] = b10[tid]; sm[BIAS+128 + tid] = b20[tid];
        sm[BIAS+256 + tid] = b11[tid]; sm[BIAS+384 + tid] = b21[tid];
        sm[BIAS+512 + tid] = b12[tid]; sm[BIAS+640 + tid] = b22[tid];
    }
    if (tid < 384) sm[WOUTO + tid] = wout[tid];
    if (tid < 512) {
        int r = tid >> 6, jj = tid & 63;
        sm[ACTo + (r>>2)*280 + (6+jj)*4 + (r&3)] = initF[(b0+r)*66 + 2 + jj];
    }

    float wl2a[32], wl2b[32];
#pragma unroll
    for (int i = 0; i < 32; i++) {
        wl2a[i] = w12[(i*4+c)*128 + j];
        wl2b[i] = w22[(i*4+c)*128 + j];
    }
    const float bav = ba[jq], bbv = bb[jq];
    const float* wap = wa + c8*64 + jq;   // element i at wap[i*512]
    const float* wbp = wb + c8*64 + jq;

    const int xr = tid / 6, xd = tid - 6*xr;
    float xc = 0.f;
    if (tid < 48) sm[XBo + tid] = x[((size_t)(b0+xr)*TST)*6 + xd];
    __syncthreads();
    if (tid < 8) {
        float s = 0.f;
#pragma unroll
        for (int d = 0; d < 6; d++){ float v = sm[XBo + tid*6 + d]; s = fmaf(v,v,s); }
        float nrm = sqrtf(s); sm[NBo + tid] = nrm;
        float inv = 1.0f/(nrm + EPSF);
#pragma unroll
        for (int d = 0; d < 6; d++)
            sm[ACTo + (tid>>2)*280 + d*4 + (tid&3)] = sm[XBo + tid*6 + d]*inv;
    }
    if (tid < 48) xc = x[((size_t)(b0+xr)*TST + 1)*6 + xd];

    float* outs = out;
    float* alph = out + (size_t)BATCH*TST*6;

#pragma unroll 1
    for (int t = 0; t < TST; t++) {
        __syncthreads();                           // A

        {   // L0: (j, q=c>>1, kh=c&1), K=70 split 35/35, both mats
            const int q = c >> 1, kh = c & 1;
            const float* ap  = sm + ACTo + q*280 + kh*140;
            const float* w1p = sm + W10O + j*71 + kh*35;
            const float* w2p = sm + W20O + j*71 + kh*35;
            ull a00=0,a01=0,a10=0,a11=0;
            if (!kh) {
                a00 = a01 = pack2(sm[BIAS+j], sm[BIAS+j]);
                a10 = a11 = pack2(sm[BIAS+128+j], sm[BIAS+128+j]);
            }
#pragma unroll 7
            for (int i = 0; i < 35; i++) {
                ull2 qv = *(const ull2*)(ap + i*4);
                ull w1d = pack2(w1p[i], w1p[i]);
                ull w2d = pack2(w2p[i], w2p[i]);
                ffma2(a00,qv.x,w1d); ffma2(a01,qv.y,w1d);
                ffma2(a10,qv.x,w2d); ffma2(a11,qv.y,w2d);
            }
            red1(a00); red1(a01); red1(a10); red1(a11);
            ull u1 = kh ? a01 : a00, u2 = kh ? a11 : a10;
            float t1,t2,t3,t4; unpack2(u1,t1,t2); unpack2(u2,t3,t4);
            *(ull*)(sm + SCRA + q*516 + j*4 + kh*2) =
                pack2(tanhf(t1)*tanhf(t3), tanhf(t2)*tanhf(t4));
        }
        __syncthreads();                           // B

        {   // L1: (j, kq=c), k=i*4+c, both mats, 8 rows, SMEM weights
            const float* a0p = sm + SCRA + c*4;
            const float* a1p = sm + SCRA + 516 + c*4;
            const float* w1p = sm + W11S + j*132 + c*33;
            const float* w2p = sm + W21S + j*132 + c*33;
            ull m0=0,m1=0,m2=0,m3=0,n0=0,n1=0,n2=0,n3=0;
            if (!c) {
                m0=m1=m2=m3 = pack2(sm[BIAS+256+j], sm[BIAS+256+j]);
                n0=n1=n2=n3 = pack2(sm[BIAS+384+j], sm[BIAS+384+j]);
            }
#pragma unroll 8
            for (int i = 0; i < 32; i++) {
                ull2 qa = *(const ull2*)(a0p + i*16);
                ull2 qb = *(const ull2*)(a1p + i*16);
                ull w1d = pack2(w1p[i], w1p[i]);
                ull w2d = pack2(w2p[i], w2p[i]);
                ffma2(m0,qa.x,w1d); ffma2(m1,qa.y,w1d); ffma2(m2,qb.x,w1d); ffma2(m3,qb.y,w1d);
                ffma2(n0,qa.x,w2d); ffma2(n1,qa.y,w2d); ffma2(n2,qb.x,w2d); ffma2(n3,qb.y,w2d);
            }
            red1(m0);red1(m1);red1(m2);red1(m3);red1(n0);red1(n1);red1(n2);red1(n3);
            m0=addx2(m0,shflx(m0,2)); m1=addx2(m1,shflx(m1,2));
            m2=addx2(m2,shflx(m2,2)); m3=addx2(m3,shflx(m3,2));
            n0=addx2(n0,shflx(n0,2)); n1=addx2(n1,shflx(n1,2));
            n2=addx2(n2,shflx(n2,2)); n3=addx2(n3,shflx(n3,2));
            ull u1 = sel4(m0,m1,m2,m3,c), u2 = sel4(n0,n1,n2,n3,c);
            float t1,t2,t3,t4; unpack2(u1,t1,t2); unpack2(u2,t3,t4);
            *(ull*)(sm + SCRB + (c>>1)*516 + j*4 + (c&1)*2) =
                pack2(tanhf(t1)*tanhf(t3), tanhf(t2)*tanhf(t4));
        }
        __syncthreads();                           // C

        {   // L2: (j, kq=c), register weights, gate = tanh(x1*x2)
            const float* a0p = sm + SCRB + c*4;
            const float* a1p = sm + SCRB + 516 + c*4;
            ull m0=0,m1=0,m2=0,m3=0,n0=0,n1=0,n2=0,n3=0;
            if (!c) {
                m0=m1=m2=m3 = pack2(sm[BIAS+512+j], sm[BIAS+512+j]);
                n0=n1=n2=n3 = pack2(sm[BIAS+640+j], sm[BIAS+640+j]);
            }
#pragma unroll 8
            for (int i = 0; i < 32; i++) {
                ull2 qa = *(const ull2*)(a0p + i*16);
                ull2 qb = *(const ull2*)(a1p + i*16);
                ull w1d = pack2(wl2a[i], wl2a[i]);
                ull w2d = pack2(wl2b[i], wl2b[i]);
                ffma2(m0,qa.x,w1d); ffma2(m1,qa.y,w1d); ffma2(m2,qb.x,w1d); ffma2(m3,qb.y,w1d);
                ffma2(n0,qa.x,w2d); ffma2(n1,qa.y,w2d); ffma2(n2,qb.x,w2d); ffma2(n3,qb.y,w2d);
            }
            red1(m0);red1(m1);red1(m2);red1(m3);red1(n0);red1(n1);red1(n2);red1(n3);
            m0=addx2(m0,shflx(m0,2)); m1=addx2(m1,shflx(m1,2));
            m2=addx2(m2,shflx(m2,2)); m3=addx2(m3,shflx(m3,2));
            n0=addx2(n0,shflx(n0,2)); n1=addx2(n1,shflx(n1,2));
            n2=addx2(n2,shflx(n2,2)); n3=addx2(n3,shflx(n3,2));
            ull u = mulx2(sel4(m0,m1,m2,m3,c), sel4(n0,n1,n2,n3,c));
            float g0,g1; unpack2(u,g0,g1);
            *(ull*)(sm + SCRA + (c>>1)*516 + j*4 + (c&1)*2) = pack2(tanhf(g0), tanhf(g1));
        }
        __syncthreads();                           // D

        {   // heads: (jq, c8), k=i*8+c8, wa/wb via __ldg, 8 rows
            const float* a0p = sm + SCRA + c8*4;
            const float* a1p = sm + SCRA + 516 + c8*4;
            ull A0=0,A1=0,A2=0,A3=0,B0=0,B1=0,B2=0,B3=0;
#pragma unroll 4
            for (int i = 0; i < 16; i++) {
                float va = __ldg(wap + (size_t)i*512);
                float vb = __ldg(wbp + (size_t)i*512);
                ull2 qa = *(const ull2*)(a0p + i*32);
                ull2 qb = *(const ull2*)(a1p + i*32);
                ull wad = pack2(va,va), wbd = pack2(vb,vb);
                ffma2(A0,qa.x,wad); ffma2(A1,qa.y,wad); ffma2(A2,qb.x,wad); ffma2(A3,qb.y,wad);
                ffma2(B0,qa.x,wbd); ffma2(B1,qa.y,wbd); ffma2(B2,qb.x,wbd); ffma2(B3,qb.y,wbd);
            }
#pragma unroll
            for (int lv = 1; lv <= 4; lv <<= 1) {
                A0=addx2(A0,shflx(A0,lv)); A1=addx2(A1,shflx(A1,lv));
                A2=addx2(A2,shflx(A2,lv)); A3=addx2(A3,shflx(A3,lv));
                B0=addx2(B0,shflx(B0,lv)); B1=addx2(B1,shflx(B1,lv));
                B2=addx2(B2,shflx(B2,lv)); B3=addx2(B3,shflx(B3,lv));
            }
            if (c8 < 4) {
                const int p = c8;
                ull ua = sel4(A0,A1,A2,A3,p), ub = sel4(B0,B1,B2,B3,p);
                float pa0,pa1,pb0,pb1; unpack2(ua,pa0,pa1); unpack2(ub,pb0,pb1);
                float al0 = expf(pa0 + bav), al1 = expf(pa1 + bav);
                float be0 = tanhf(pb0 + bbv), be1 = tanhf(pb1 + bbv);
                const int hoff = ACTo + (p>>1)*280 + (6+jq)*4 + (p&1)*2;
                ull hv = *(const ull*)(sm + hoff);
                float h0,h1; unpack2(hv,h0,h1);
                float hn0 = fmaf(expf(-al0*sm[NBo+2*p]),   h0-be0, be0);
                float hn1 = fmaf(expf(-al1*sm[NBo+2*p+1]), h1-be1, be1);
                *(ull*)(sm + hoff) = pack2(hn0,hn1);
                alph[((size_t)(b0+2*p)*TST + t)*64 + jq]   = al0;
                alph[((size_t)(b0+2*p+1)*TST + t)*64 + jq] = al1;
            }
            if (tid < 48 && t+1 < TST) sm[XBo + tid] = xc;   // stage x(t+1)
        }
        __syncthreads();                           // E

        if (tid < 48) {   // outs = h @ wout; prefetch x(t+2)
            const int r = tid/6, o = tid - 6*r;
            const int base = ACTo + (r>>2)*280 + (r&3);
            float acc = 0.f;
#pragma unroll
            for (int k = 0; k < 64; k++)
                acc = fmaf(sm[base + (6+k)*4], sm[WOUTO + k*6 + o], acc);
            outs[((size_t)(b0+r)*TST + t)*6 + o] = acc;
            if (t+2 < TST) xc = x[((size_t)(b0+xr)*TST + (t+2))*6 + xd];
        }
        if (tid < 8 && t+1 < TST) {   // norm + xn for t+1
            float s = 0.f;
#pragma unroll
            for (int d = 0; d < 6; d++){ float v = sm[XBo + tid*6 + d]; s = fmaf(v,v,s); }
            float nrm = sqrtf(s); sm[NBo + tid] = nrm;
            float inv = 1.0f/(nrm + EPSF);
#pragma unroll
            for (int d = 0; d < 6; d++)
                sm[ACTo + (tid>>2)*280 + d*4 + (tid&3)] = sm[XBo + tid*6 + d]*inv;
        }
    }
}

extern "C" void kernel_launch(void* const* d_in, const int* in_sizes, int n_in,
                              void* d_out, int out_size)
{
    const float* x    =(const float*)d_in[0];  const float* initF=(const float*)d_in[1];
    const float* w10  =(const float*)d_in[2];  const float* b10  =(const float*)d_in[3];
    const float* w20  =(const float*)d_in[4];  const float* b20  =(const float*)d_in[5];
    const float* w11  =(const float*)d_in[6];  const float* b11  =(const float*)d_in[7];
    const float* w21  =(const float*)d_in[8];  const float* b21  =(const float*)d_in[9];
    const float* w12  =(const float*)d_in[10]; const float* b12  =(const float*)d_in[11];
    const float* w22  =(const float*)d_in[12]; const float* b22  =(const float*)d_in[13];
    const float* wa   =(const float*)d_in[14]; const float* ba   =(const float*)d_in[15];
    const float* wb   =(const float*)d_in[16]; const float* bb   =(const float*)d_in[17];
    const float* wout =(const float*)d_in[18];
    float* out = (float*)d_out;

    const int smem_bytes = SMF * 4;
    cudaFuncSetAttribute(lmsc_kernel, cudaFuncAttributeMaxDynamicSharedMemorySize, smem_bytes);
    lmsc_kernel<<<BATCH/8, NTH, smem_bytes>>>(x, initF, w10,b10,w20,b20, w11,b11,w21,b21,
                                              w12,b12,w22,b22, wa,ba,wb,bb, wout, out);
}